// round 4
// baseline (speedup 1.0000x reference)
#include <cuda_runtime.h>

#define NP 16384   // N_POINTS
#define NS 8192    // N_SAMPLES
#define KCHUNK 256
#define NKCH (NS / KCHUNK)   // 32 k-chunks
#define TPB 256
#define PPT 8                // points per thread
#define IBLK (TPB * PPT)     // 2048 i-points per block
#define NIB (NS / IBLK)      // 4 i-blocks

typedef unsigned long long u64;

// Scratch (no device allocations allowed)
__device__ float4 g_b[NS];                 // (-2bx, -2by, -2bz, ||b||^2)
__device__ float  g_ax[NS], g_ay[NS], g_az[NS], g_sqa[NS];
__device__ float  g_partial[NKCH * NS];    // partial mins [kchunk][i]

__device__ __forceinline__ u64 pack2(float lo, float hi) {
    u64 r;
    asm("mov.b64 %0, {%1, %2};" : "=l"(r) : "f"(lo), "f"(hi));
    return r;
}
__device__ __forceinline__ void unpack2(u64 v, float& lo, float& hi) {
    asm("mov.b64 {%0, %1}, %2;" : "=f"(lo), "=f"(hi) : "l"(v));
}
__device__ __forceinline__ u64 fma2(u64 a, u64 b, u64 c) {
    u64 d;
    asm("fma.rn.f32x2 %0, %1, %2, %3;" : "=l"(d) : "l"(a), "l"(b), "l"(c));
    return d;
}

__global__ void gather_kernel(const float* __restrict__ a,
                              const float* __restrict__ b,
                              const int* __restrict__ a_idx,
                              const int* __restrict__ b_idx,
                              float* __restrict__ out) {
    int i = blockIdx.x * blockDim.x + threadIdx.x;
    if (i == 0) *out = 0.0f;   // d_out is poisoned; zero it before reduce
    if (i >= NS) return;

    int ia = a_idx[i];
    float ax = a[ia], ay = a[NP + ia], az = a[2 * NP + ia];
    g_ax[i] = ax; g_ay[i] = ay; g_az[i] = az;
    g_sqa[i] = ax * ax + ay * ay + az * az;

    int ib = b_idx[i];
    float bx = b[ib], by = b[NP + ib], bz = b[2 * NP + ib];
    g_b[i] = make_float4(-2.0f * bx, -2.0f * by, -2.0f * bz,
                         bx * bx + by * by + bz * bz);
}

__global__ __launch_bounds__(TPB) void dist_kernel() {
    // SoA so two consecutive k's load as one broadcast LDS.64
    __shared__ __align__(8) float sbx[KCHUNK], sby[KCHUNK], sbz[KCHUNK], sbw[KCHUNK];
    const int t = threadIdx.x;
    const int ibase = blockIdx.x * IBLK + t;
    const int kbase = blockIdx.y * KCHUNK;

    {
        float4 v = g_b[kbase + t];
        sbx[t] = v.x; sby[t] = v.y; sbz[t] = v.z; sbw[t] = v.w;
    }

    u64 ax2[PPT], ay2[PPT], az2[PPT];
    float mn_e[PPT], mn_o[PPT];
    #pragma unroll
    for (int r = 0; r < PPT; r++) {
        int i = ibase + r * TPB;
        float ax = g_ax[i], ay = g_ay[i], az = g_az[i];
        ax2[r] = pack2(ax, ax);
        ay2[r] = pack2(ay, ay);
        az2[r] = pack2(az, az);
        mn_e[r] = 3.4e38f; mn_o[r] = 3.4e38f;
    }
    __syncthreads();

    #pragma unroll 4
    for (int k = 0; k < KCHUNK; k += 2) {
        u64 bx2 = *reinterpret_cast<const u64*>(&sbx[k]);
        u64 by2 = *reinterpret_cast<const u64*>(&sby[k]);
        u64 bz2 = *reinterpret_cast<const u64*>(&sbz[k]);
        u64 bw2 = *reinterpret_cast<const u64*>(&sbw[k]);
        #pragma unroll
        for (int r = 0; r < PPT; r++) {
            // packed over two k's: ||b||^2 - 2 b.a  (||a||^2 added in reduce)
            u64 d2 = fma2(bx2, ax2[r], fma2(by2, ay2[r], fma2(bz2, az2[r], bw2)));
            float dl, dh;
            unpack2(d2, dl, dh);
            mn_e[r] = fminf(mn_e[r], dl);   // independent accumulators:
            mn_o[r] = fminf(mn_o[r], dh);   // no serial FMNMX chain
        }
    }

    #pragma unroll
    for (int r = 0; r < PPT; r++)
        g_partial[blockIdx.y * NS + ibase + r * TPB] = fminf(mn_e[r], mn_o[r]);
}

__global__ __launch_bounds__(256) void reduce_kernel(float* __restrict__ out) {
    int i = blockIdx.x * blockDim.x + threadIdx.x;
    float m = g_partial[i];
    #pragma unroll
    for (int c = 1; c < NKCH; c++)
        m = fminf(m, g_partial[c * NS + i]);
    float v = m + g_sqa[i];

    __shared__ float ssum[8];
    #pragma unroll
    for (int o = 16; o > 0; o >>= 1)
        v += __shfl_down_sync(0xffffffffu, v, o);
    if ((threadIdx.x & 31) == 0) ssum[threadIdx.x >> 5] = v;
    __syncthreads();
    if (threadIdx.x < 8) {
        v = ssum[threadIdx.x];
        #pragma unroll
        for (int o = 4; o > 0; o >>= 1)
            v += __shfl_down_sync(0xffu, v, o);
        if (threadIdx.x == 0) atomicAdd(out, v);
    }
}

extern "C" void kernel_launch(void* const* d_in, const int* in_sizes, int n_in,
                              void* d_out, int out_size) {
    const float* a  = (const float*)d_in[0];
    const float* b  = (const float*)d_in[1];
    const int*   ai = (const int*)d_in[2];
    const int*   bi = (const int*)d_in[3];
    float* out = (float*)d_out;

    gather_kernel<<<(NS + 255) / 256, 256>>>(a, b, ai, bi, out);
    dist_kernel<<<dim3(NIB, NKCH), TPB>>>();
    reduce_kernel<<<NS / 256, 256>>>(out);
}